// round 2
// baseline (speedup 1.0000x reference)
#include <cuda_runtime.h>
#include <math.h>

#define N_NODES 50000
#define NEG_SLOPE 0.2f

// ---------------- device scratch (no allocs allowed) ----------------
__device__ float g_h1  [(size_t)N_NODES * 128];
__device__ float g_acc1[(size_t)N_NODES * 128];
__device__ float g_hid [(size_t)N_NODES * 128];
__device__ float g_h2  [(size_t)N_NODES * 64];
__device__ float g_acc2[(size_t)N_NODES * 64];
__device__ float g_asrc[N_NODES];
__device__ float g_adst[N_NODES];
__device__ float g_denom[N_NODES];
__device__ int   g_idx64;

// ---------------- dtype detection for edge_index (int32 vs int64) ----------------
// int64 little-endian values < 2^31 -> every odd 32-bit word is 0.
__global__ void detect_idx_dtype(const int* __restrict__ ei32) {
    int z = 1;
    for (int i = 1; i < 256; i += 2)
        if (ei32[i] != 0) { z = 0; break; }
    g_idx64 = z;
}

// ---------------- simple register-tiled fp32 GEMM ----------------
// A: [M,K] row-major, B: [K,N] row-major, C: [M,N]. K%BK==0, N%BN==0 guaranteed.
template <int BM, int BN, int BK, int TM, int TN>
__global__ void gemm_kernel(const float* __restrict__ A, const float* __restrict__ B,
                            float* __restrict__ C, int M, int N, int K) {
    __shared__ float As[BM][BK];
    __shared__ float Bs[BK][BN];
    const int nThreads = (BM / TM) * (BN / TN);
    int tid = threadIdx.x;
    int tRow = tid / (BN / TN);
    int tCol = tid % (BN / TN);
    int blockRow = blockIdx.y * BM;
    int blockCol = blockIdx.x * BN;

    float acc[TM][TN];
#pragma unroll
    for (int i = 0; i < TM; i++)
#pragma unroll
        for (int j = 0; j < TN; j++) acc[i][j] = 0.f;

    for (int k0 = 0; k0 < K; k0 += BK) {
        for (int i = tid; i < BM * BK; i += nThreads) {
            int r = i / BK, c = i % BK;
            int gr = blockRow + r;
            As[r][c] = (gr < M) ? A[(size_t)gr * K + k0 + c] : 0.f;
        }
        for (int i = tid; i < BK * BN; i += nThreads) {
            int r = i / BN, c = i % BN;
            Bs[r][c] = B[(size_t)(k0 + r) * N + blockCol + c];
        }
        __syncthreads();
#pragma unroll
        for (int kk = 0; kk < BK; kk++) {
            float a[TM], b[TN];
#pragma unroll
            for (int i = 0; i < TM; i++) a[i] = As[tRow * TM + i][kk];
#pragma unroll
            for (int j = 0; j < TN; j++) b[j] = Bs[kk][tCol * TN + j];
#pragma unroll
            for (int i = 0; i < TM; i++)
#pragma unroll
                for (int j = 0; j < TN; j++) acc[i][j] += a[i] * b[j];
        }
        __syncthreads();
    }
#pragma unroll
    for (int i = 0; i < TM; i++) {
        int gr = blockRow + tRow * TM + i;
        if (gr >= M) continue;
#pragma unroll
        for (int j = 0; j < TN; j++)
            C[(size_t)gr * N + blockCol + tCol * TN + j] = acc[i][j];
    }
}

// ---------------- per-node prep: attention dots + zero accumulators ----------------
template <int C>
__global__ void node_prep(const float* __restrict__ h,
                          const float* __restrict__ att_s, const float* __restrict__ att_d,
                          float* __restrict__ asrc, float* __restrict__ adst,
                          float* __restrict__ acc, float* __restrict__ denom) {
    int warp = (blockIdx.x * blockDim.x + threadIdx.x) >> 5;
    int lane = threadIdx.x & 31;
    if (warp >= N_NODES) return;
    float ss = 0.f, sd = 0.f;
    const float* hrow = h + (size_t)warp * C;
    float* arow = acc + (size_t)warp * C;
#pragma unroll
    for (int j = lane; j < C; j += 32) {
        float v = hrow[j];
        ss += v * att_s[j];
        sd += v * att_d[j];
        arow[j] = 0.f;
    }
#pragma unroll
    for (int o = 16; o > 0; o >>= 1) {
        ss += __shfl_down_sync(0xffffffffu, ss, o);
        sd += __shfl_down_sync(0xffffffffu, sd, o);
    }
    if (lane == 0) {
        asrc[warp] = ss;
        adst[warp] = sd;
        denom[warp] = 0.f;
    }
}

// ---------------- fused edge pass: softmax numerator + weighted aggregation ----------------
// one warp per edge; indices >= E are self-loops (src=dst=idx-E)
template <int C>
__global__ void edge_agg(const void* __restrict__ ei_raw, int E,
                         const float* __restrict__ h,
                         const float* __restrict__ asrc, const float* __restrict__ adst,
                         float* __restrict__ acc, float* __restrict__ denom) {
    int warp = (blockIdx.x * blockDim.x + threadIdx.x) >> 5;
    int lane = threadIdx.x & 31;
    if (warp >= E + N_NODES) return;
    int s, d;
    if (warp < E) {
        if (g_idx64) {
            const long long* p = (const long long*)ei_raw;
            s = (int)p[warp];
            d = (int)p[(size_t)E + warp];
        } else {
            const int* p = (const int*)ei_raw;
            s = p[warp];
            d = p[E + warp];
        }
    } else {
        s = d = warp - E;
    }
    float e = asrc[s] + adst[d];
    e = (e > 0.f) ? e : NEG_SLOPE * e;
    float ee = __expf(e);
    if (lane == 0) atomicAdd(denom + d, ee);

    if (C == 128) {
        const float4* hv4 = (const float4*)(h + (size_t)s * C);
        float4* av4 = (float4*)(acc + (size_t)d * C);
        float4 hv = hv4[lane];
#if __CUDA_ARCH__ >= 900
        atomicAdd(av4 + lane, make_float4(hv.x * ee, hv.y * ee, hv.z * ee, hv.w * ee));
#else
        float* a = (float*)(av4 + lane);
        atomicAdd(a + 0, hv.x * ee); atomicAdd(a + 1, hv.y * ee);
        atomicAdd(a + 2, hv.z * ee); atomicAdd(a + 3, hv.w * ee);
#endif
    } else {  // C == 64
        const float2* hv2 = (const float2*)(h + (size_t)s * C);
        float2* av2 = (float2*)(acc + (size_t)d * C);
        float2 hv = hv2[lane];
#if __CUDA_ARCH__ >= 900
        atomicAdd(av2 + lane, make_float2(hv.x * ee, hv.y * ee));
#else
        float* a = (float*)(av2 + lane);
        atomicAdd(a + 0, hv.x * ee); atomicAdd(a + 1, hv.y * ee);
#endif
    }
}

// ---------------- finalize layer 1: divide, bias, ReLU ----------------
__global__ void finalize1(const float* __restrict__ acc, const float* __restrict__ denom,
                          const float* __restrict__ bias, float* __restrict__ out) {
    int i = blockIdx.x * blockDim.x + threadIdx.x;
    if (i >= N_NODES * 128) return;
    int node = i >> 7;
    int c = i & 127;
    float v = acc[i] / denom[node] + bias[c];
    out[i] = (v > 0.f) ? v : 0.f;
}

// ---------------- finalize layer 2: divide, bias, log_softmax (C=64, warp/node) ----------------
__global__ void finalize2(const float* __restrict__ acc, const float* __restrict__ denom,
                          const float* __restrict__ bias, float* __restrict__ out) {
    int warp = (blockIdx.x * blockDim.x + threadIdx.x) >> 5;
    int lane = threadIdx.x & 31;
    if (warp >= N_NODES) return;
    float dn = denom[warp];
    size_t base = (size_t)warp * 64;
    float v0 = acc[base + lane] / dn + bias[lane];
    float v1 = acc[base + 32 + lane] / dn + bias[32 + lane];
    float m = fmaxf(v0, v1);
#pragma unroll
    for (int o = 16; o > 0; o >>= 1) m = fmaxf(m, __shfl_xor_sync(0xffffffffu, m, o));
    float sm = __expf(v0 - m) + __expf(v1 - m);
#pragma unroll
    for (int o = 16; o > 0; o >>= 1) sm += __shfl_xor_sync(0xffffffffu, sm, o);
    float lse = m + logf(sm);
    out[base + lane] = v0 - lse;
    out[base + 32 + lane] = v1 - lse;
}

// ---------------- host orchestration ----------------
extern "C" void kernel_launch(void* const* d_in, const int* in_sizes, int n_in,
                              void* d_out, int out_size) {
    const float* x   = (const float*)d_in[0];
    const void*  ei  = d_in[1];
    const float* W1  = (const float*)d_in[2];
    const float* as1 = (const float*)d_in[3];
    const float* ad1 = (const float*)d_in[4];
    const float* b1  = (const float*)d_in[5];
    const float* W2  = (const float*)d_in[6];
    const float* as2 = (const float*)d_in[7];
    const float* ad2 = (const float*)d_in[8];
    const float* b2  = (const float*)d_in[9];
    float* out = (float*)d_out;

    int E = in_sizes[1] / 2;

    float *h1, *acc1, *hid, *h2, *acc2, *asrc, *adst, *denom;
    cudaGetSymbolAddress((void**)&h1,   g_h1);
    cudaGetSymbolAddress((void**)&acc1, g_acc1);
    cudaGetSymbolAddress((void**)&hid,  g_hid);
    cudaGetSymbolAddress((void**)&h2,   g_h2);
    cudaGetSymbolAddress((void**)&acc2, g_acc2);
    cudaGetSymbolAddress((void**)&asrc, g_asrc);
    cudaGetSymbolAddress((void**)&adst, g_adst);
    cudaGetSymbolAddress((void**)&denom, g_denom);

    detect_idx_dtype<<<1, 1>>>((const int*)ei);

    const int nodeWarpBlocks = (N_NODES * 32 + 255) / 256;
    const int edgeWarpBlocks = ((E + N_NODES) * 32 + 255) / 256;  // fits int: 27.2M

    // ===== Layer 1 =====
    {
        dim3 grid(128 / 64, (N_NODES + 63) / 64);
        gemm_kernel<64, 64, 16, 4, 4><<<grid, 256>>>(x, W1, h1, N_NODES, 128, 256);
    }
    node_prep<128><<<nodeWarpBlocks, 256>>>(h1, as1, ad1, asrc, adst, acc1, denom);
    edge_agg<128><<<edgeWarpBlocks, 256>>>(ei, E, h1, asrc, adst, acc1, denom);
    finalize1<<<(N_NODES * 128 + 255) / 256, 256>>>(acc1, denom, b1, hid);

    // ===== Layer 2 =====
    {
        dim3 grid(64 / 64, (N_NODES + 63) / 64);
        gemm_kernel<64, 64, 16, 4, 4><<<grid, 256>>>(hid, W2, h2, N_NODES, 64, 128);
    }
    node_prep<64><<<nodeWarpBlocks, 256>>>(h2, as2, ad2, asrc, adst, acc2, denom);
    edge_agg<64><<<edgeWarpBlocks, 256>>>(ei, E, h2, asrc, adst, acc2, denom);
    finalize2<<<nodeWarpBlocks, 256>>>(acc2, denom, b2, out);
}

// round 3
// speedup vs baseline: 2.7579x; 2.7579x over previous
#include <cuda_runtime.h>
#include <math.h>

#define N_NODES 50000
#define NEG_SLOPE 0.2f
#define MAX_E 1200000
#define SCAN_CHUNK 512
#define NUM_SCAN_BLOCKS ((N_NODES + SCAN_CHUNK - 1) / SCAN_CHUNK)

// ---------------- device scratch (no allocs allowed) ----------------
__device__ float g_h1 [(size_t)N_NODES * 128];
__device__ float g_hid[(size_t)N_NODES * 128];
__device__ float g_h2 [(size_t)N_NODES * 64];
__device__ float g_asrc[N_NODES];
__device__ float g_adst[N_NODES];
__device__ int   g_cnt[N_NODES];
__device__ int   g_rowptr[N_NODES + 1];
__device__ int   g_cur[N_NODES];
__device__ int   g_col[MAX_E];
__device__ int   g_bsum[NUM_SCAN_BLOCKS + 1];
__device__ int   g_idx64;

__device__ __forceinline__ float leaky_exp(float e) {
    e = (e > 0.f) ? e : NEG_SLOPE * e;
    return __expf(e);
}

// ---------------- dtype detection for edge_index (int32 vs int64) ----------------
__global__ void detect_idx_dtype(const int* __restrict__ ei32) {
    int z = 1;
    for (int i = 1; i < 256; i += 2)
        if (ei32[i] != 0) { z = 0; break; }
    g_idx64 = z;
}

// ---------------- CSR build ----------------
__global__ void zero_counts(int* __restrict__ cnt) {
    int i = blockIdx.x * blockDim.x + threadIdx.x;
    if (i < N_NODES) cnt[i] = 0;
}

__global__ void count_edges(const void* __restrict__ ei, int E, int* __restrict__ cnt) {
    int i = blockIdx.x * blockDim.x + threadIdx.x;
    if (i >= E) return;
    int d;
    if (g_idx64) d = (int)((const long long*)ei)[(size_t)E + i];
    else         d = ((const int*)ei)[E + i];
    atomicAdd(cnt + d, 1);
}

__global__ void scan_block(const int* __restrict__ cnt, int* __restrict__ rowptr,
                           int* __restrict__ bsum) {
    __shared__ int sm[SCAN_CHUNK];
    int b = blockIdx.x, t = threadIdx.x;
    int i = b * SCAN_CHUNK + t;
    int v = (i < N_NODES) ? cnt[i] : 0;
    sm[t] = v;
    __syncthreads();
#pragma unroll
    for (int o = 1; o < SCAN_CHUNK; o <<= 1) {
        int x = (t >= o) ? sm[t - o] : 0;
        __syncthreads();
        sm[t] += x;
        __syncthreads();
    }
    if (i < N_NODES) rowptr[i] = sm[t] - v;  // exclusive
    if (t == SCAN_CHUNK - 1) bsum[b] = sm[t];
}

__global__ void scan_bsums(int* __restrict__ bsum) {
    __shared__ int sm[NUM_SCAN_BLOCKS];
    int t = threadIdx.x;
    if (t < NUM_SCAN_BLOCKS) sm[t] = bsum[t];
    __syncthreads();
    if (t == 0) {
        int acc = 0;
        for (int i = 0; i < NUM_SCAN_BLOCKS; i++) { int v = sm[i]; sm[i] = acc; acc += v; }
    }
    __syncthreads();
    if (t < NUM_SCAN_BLOCKS) bsum[t] = sm[t];
}

__global__ void add_offsets(int* __restrict__ rowptr, const int* __restrict__ bsum,
                            int* __restrict__ cur, int E) {
    int i = blockIdx.x * blockDim.x + threadIdx.x;
    if (i < N_NODES) {
        int r = rowptr[i] + bsum[i / SCAN_CHUNK];
        rowptr[i] = r;
        cur[i] = r;
    }
    if (i == 0) rowptr[N_NODES] = E;
}

__global__ void scatter_edges(const void* __restrict__ ei, int E,
                              int* __restrict__ cur, int* __restrict__ col) {
    int i = blockIdx.x * blockDim.x + threadIdx.x;
    if (i >= E) return;
    int s, d;
    if (g_idx64) {
        const long long* p = (const long long*)ei;
        s = (int)p[i];
        d = (int)p[(size_t)E + i];
    } else {
        const int* p = (const int*)ei;
        s = p[i];
        d = p[E + i];
    }
    int pos = atomicAdd(cur + d, 1);
    col[pos] = s;
}

// ---------------- SGEMM: BMxBN tile, TMxTN per-thread microtile ----------------
// A [M,K] row-major, B [K,N] row-major, C [M,N]. K%BK==0, N%BN==0.
template <int BM, int BN, int BK, int TM, int TN>
__global__ void sgemm(const float* __restrict__ A, const float* __restrict__ B,
                      float* __restrict__ C, int M, int N, int K) {
    constexpr int nThreads = (BM / TM) * (BN / TN);
    constexpr int TCOLS = BN / TN;
    __shared__ float As[BK][BM];  // transposed A tile
    __shared__ float Bs[BK][BN];

    int tid = threadIdx.x;
    int tRow = tid / TCOLS;
    int tCol = tid % TCOLS;
    int row0 = blockIdx.y * BM;
    int col0 = blockIdx.x * BN;

    float acc[TM][TN];
#pragma unroll
    for (int i = 0; i < TM; i++)
#pragma unroll
        for (int j = 0; j < TN; j++) acc[i][j] = 0.f;

    for (int k0 = 0; k0 < K; k0 += BK) {
        // load A tile (transposed into As)
#pragma unroll
        for (int i = tid; i < BM * BK / 4; i += nThreads) {
            int aRow = i / (BK / 4);
            int ac = i % (BK / 4);
            int gr = row0 + aRow;
            float4 v = make_float4(0.f, 0.f, 0.f, 0.f);
            if (gr < M) v = *(const float4*)(A + (size_t)gr * K + k0 + ac * 4);
            As[ac * 4 + 0][aRow] = v.x;
            As[ac * 4 + 1][aRow] = v.y;
            As[ac * 4 + 2][aRow] = v.z;
            As[ac * 4 + 3][aRow] = v.w;
        }
        // load B tile
#pragma unroll
        for (int i = tid; i < BK * BN / 4; i += nThreads) {
            int bRow = i / (BN / 4);
            int bc = i % (BN / 4);
            *(float4*)&Bs[bRow][bc * 4] =
                *(const float4*)(B + (size_t)(k0 + bRow) * N + col0 + bc * 4);
        }
        __syncthreads();
#pragma unroll
        for (int kk = 0; kk < BK; kk++) {
            float a[TM], b[TN];
#pragma unroll
            for (int i = 0; i < TM; i += 4)
                *(float4*)&a[i] = *(const float4*)&As[kk][tRow * TM + i];
#pragma unroll
            for (int j = 0; j < TN; j += 4)
                *(float4*)&b[j] = *(const float4*)&Bs[kk][tCol * TN + j];
#pragma unroll
            for (int i = 0; i < TM; i++)
#pragma unroll
                for (int j = 0; j < TN; j++) acc[i][j] += a[i] * b[j];
        }
        __syncthreads();
    }
#pragma unroll
    for (int i = 0; i < TM; i++) {
        int gr = row0 + tRow * TM + i;
        if (gr >= M) continue;
#pragma unroll
        for (int j = 0; j < TN; j += 4)
            *(float4*)(C + (size_t)gr * N + col0 + tCol * TN + j) = *(float4*)&acc[i][j];
    }
}

// ---------------- per-node attention dots ----------------
template <int C>
__global__ void node_dots(const float* __restrict__ h,
                          const float* __restrict__ att_s, const float* __restrict__ att_d,
                          float* __restrict__ asrc, float* __restrict__ adst) {
    int warp = (blockIdx.x * blockDim.x + threadIdx.x) >> 5;
    int lane = threadIdx.x & 31;
    if (warp >= N_NODES) return;
    float ss = 0.f, sd = 0.f;
    const float* hrow = h + (size_t)warp * C;
#pragma unroll
    for (int j = lane; j < C; j += 32) {
        float v = hrow[j];
        ss += v * att_s[j];
        sd += v * att_d[j];
    }
#pragma unroll
    for (int o = 16; o > 0; o >>= 1) {
        ss += __shfl_down_sync(0xffffffffu, ss, o);
        sd += __shfl_down_sync(0xffffffffu, sd, o);
    }
    if (lane == 0) {
        asrc[warp] = ss;
        adst[warp] = sd;
    }
}

// ---------------- fused gather-aggregate layer 1 (C=128): softmax + bias + ReLU ----------------
__global__ void agg1(const int* __restrict__ rowptr, const int* __restrict__ col,
                     const float* __restrict__ h, const float* __restrict__ asrc,
                     const float* __restrict__ adst, const float* __restrict__ bias,
                     float* __restrict__ out) {
    int warp = (blockIdx.x * blockDim.x + threadIdx.x) >> 5;
    int lane = threadIdx.x & 31;
    if (warp >= N_NODES) return;
    int d = warp;
    float ad = adst[d];

    // self loop
    float ee = leaky_exp(asrc[d] + ad);
    float4 hv = ((const float4*)(h + (size_t)d * 128))[lane];
    float ax = hv.x * ee, ay = hv.y * ee, az = hv.z * ee, aw = hv.w * ee;
    float denom = ee;

    int beg = rowptr[d], end = rowptr[d + 1];
    for (int j0 = beg; j0 < end; j0 += 32) {
        int idx = j0 + lane;
        int sj = 0;
        float aj = 0.f;
        if (idx < end) { sj = col[idx]; aj = asrc[sj]; }
        int cnt = min(32, end - j0);
#pragma unroll 4
        for (int j = 0; j < cnt; j++) {
            int s = __shfl_sync(0xffffffffu, sj, j);
            float a = __shfl_sync(0xffffffffu, aj, j);
            float w = leaky_exp(a + ad);
            float4 x = ((const float4*)(h + (size_t)s * 128))[lane];
            ax += w * x.x; ay += w * x.y; az += w * x.z; aw += w * x.w;
            denom += w;
        }
    }
    float inv = 1.f / denom;
    float4 b4 = ((const float4*)bias)[lane];
    float4 o;
    o.x = fmaxf(ax * inv + b4.x, 0.f);
    o.y = fmaxf(ay * inv + b4.y, 0.f);
    o.z = fmaxf(az * inv + b4.z, 0.f);
    o.w = fmaxf(aw * inv + b4.w, 0.f);
    ((float4*)(out + (size_t)d * 128))[lane] = o;
}

// ---------------- fused gather-aggregate layer 2 (C=64): softmax + bias + log_softmax ----------------
__global__ void agg2(const int* __restrict__ rowptr, const int* __restrict__ col,
                     const float* __restrict__ h, const float* __restrict__ asrc,
                     const float* __restrict__ adst, const float* __restrict__ bias,
                     float* __restrict__ out) {
    int warp = (blockIdx.x * blockDim.x + threadIdx.x) >> 5;
    int lane = threadIdx.x & 31;
    if (warp >= N_NODES) return;
    int d = warp;
    float ad = adst[d];

    float ee = leaky_exp(asrc[d] + ad);
    float2 hv = ((const float2*)(h + (size_t)d * 64))[lane];
    float ax = hv.x * ee, ay = hv.y * ee;
    float denom = ee;

    int beg = rowptr[d], end = rowptr[d + 1];
    for (int j0 = beg; j0 < end; j0 += 32) {
        int idx = j0 + lane;
        int sj = 0;
        float aj = 0.f;
        if (idx < end) { sj = col[idx]; aj = asrc[sj]; }
        int cnt = min(32, end - j0);
#pragma unroll 4
        for (int j = 0; j < cnt; j++) {
            int s = __shfl_sync(0xffffffffu, sj, j);
            float a = __shfl_sync(0xffffffffu, aj, j);
            float w = leaky_exp(a + ad);
            float2 x = ((const float2*)(h + (size_t)s * 64))[lane];
            ax += w * x.x; ay += w * x.y;
            denom += w;
        }
    }
    float inv = 1.f / denom;
    float2 b2 = ((const float2*)bias)[lane];
    float v0 = ax * inv + b2.x;
    float v1 = ay * inv + b2.y;
    // log_softmax over the 64-wide row
    float m = fmaxf(v0, v1);
#pragma unroll
    for (int o = 16; o > 0; o >>= 1) m = fmaxf(m, __shfl_xor_sync(0xffffffffu, m, o));
    float sm = __expf(v0 - m) + __expf(v1 - m);
#pragma unroll
    for (int o = 16; o > 0; o >>= 1) sm += __shfl_xor_sync(0xffffffffu, sm, o);
    float lse = m + logf(sm);
    float2 o2;
    o2.x = v0 - lse;
    o2.y = v1 - lse;
    ((float2*)(out + (size_t)d * 64))[lane] = o2;
}

// ---------------- host orchestration ----------------
extern "C" void kernel_launch(void* const* d_in, const int* in_sizes, int n_in,
                              void* d_out, int out_size) {
    const float* x   = (const float*)d_in[0];
    const void*  ei  = d_in[1];
    const float* W1  = (const float*)d_in[2];
    const float* as1 = (const float*)d_in[3];
    const float* ad1 = (const float*)d_in[4];
    const float* b1  = (const float*)d_in[5];
    const float* W2  = (const float*)d_in[6];
    const float* as2 = (const float*)d_in[7];
    const float* ad2 = (const float*)d_in[8];
    const float* b2  = (const float*)d_in[9];
    float* out = (float*)d_out;

    int E = in_sizes[1] / 2;

    float *h1, *hid, *h2, *asrc, *adst;
    int *cnt, *rowptr, *cur, *col, *bsum;
    cudaGetSymbolAddress((void**)&h1,  g_h1);
    cudaGetSymbolAddress((void**)&hid, g_hid);
    cudaGetSymbolAddress((void**)&h2,  g_h2);
    cudaGetSymbolAddress((void**)&asrc, g_asrc);
    cudaGetSymbolAddress((void**)&adst, g_adst);
    cudaGetSymbolAddress((void**)&cnt, g_cnt);
    cudaGetSymbolAddress((void**)&rowptr, g_rowptr);
    cudaGetSymbolAddress((void**)&cur, g_cur);
    cudaGetSymbolAddress((void**)&col, g_col);
    cudaGetSymbolAddress((void**)&bsum, g_bsum);

    const int nodeBlocks = (N_NODES + 255) / 256;
    const int nodeWarpBlocks = (N_NODES * 32 + 255) / 256;
    const int edgeBlocks = (E + 255) / 256;

    detect_idx_dtype<<<1, 1>>>((const int*)ei);

    // ---- CSR build (shared by both layers) ----
    zero_counts<<<nodeBlocks, 256>>>(cnt);
    count_edges<<<edgeBlocks, 256>>>(ei, E, cnt);
    scan_block<<<NUM_SCAN_BLOCKS, SCAN_CHUNK>>>(cnt, rowptr, bsum);
    scan_bsums<<<1, 128>>>(bsum);
    add_offsets<<<nodeBlocks, 256>>>(rowptr, bsum, cur, E);
    scatter_edges<<<edgeBlocks, 256>>>(ei, E, cur, col);

    // ===== Layer 1 =====
    {
        dim3 grid(128 / 128, (N_NODES + 127) / 128);
        sgemm<128, 128, 8, 8, 8><<<grid, 256>>>(x, W1, h1, N_NODES, 128, 256);
    }
    node_dots<128><<<nodeWarpBlocks, 256>>>(h1, as1, ad1, asrc, adst);
    agg1<<<nodeWarpBlocks, 256>>>(rowptr, col, h1, asrc, adst, b1, hid);

    // ===== Layer 2 =====
    {
        dim3 grid(64 / 64, (N_NODES + 127) / 128);
        sgemm<128, 64, 8, 8, 8><<<grid, 128>>>(hid, W2, h2, N_NODES, 64, 128);
    }
    node_dots<64><<<nodeWarpBlocks, 256>>>(h2, as2, ad2, asrc, adst);
    agg2<<<nodeWarpBlocks, 256>>>(rowptr, col, h2, asrc, adst, b2, out);
}